// round 12
// baseline (speedup 1.0000x reference)
#include <cuda_runtime.h>
#include <cuda_bf16.h>
#include <mma.h>
#include <cstdint>

using namespace nvcuda;

#define Bd   2
#define Cc   128
#define Hd   64
#define Wd   512
#define HW   (Hd*Wd)          // 32768
#define NPIX (Bd*HW)          // 65536
#define EPS  1e-5f

#define LDW   136             // bf16 leading dim in smem (272B rows)
#define NPXT  64              // px per pass1 block (R7-proven)
#define LDST  68              // f32 stage leading dim
#define KILLV (-1e30f)

// ---------------- device scratch (allocation-free) ----------------
__device__ __align__(16) float g_Y[Cc * NPIX];   // [o][gp]
__device__ __align__(16) float g_E[12 * NPIX];   // [k*4+grp][gp] partial ew sums

__device__ __forceinline__ uint32_t pack_bf2(float a, float b) {
    __nv_bfloat16 ha = __float2bfloat16(a), hb = __float2bfloat16(b);
    return (uint32_t)__bfloat16_as_ushort(ha) | ((uint32_t)__bfloat16_as_ushort(hb) << 16);
}

// ---------------------------------------------------------------- pass1 (wmma, 2 CTA/SM)
// Per block: D[128 out][64 px] = (Whi+Wlo) x (Fhi+Flo)^T, 3-term bf16 split.
// W split + BN fold computed IN-BLOCK from fw (no prep kernel).
#define SEG_W 34816
#define SEG_F 17408
#define SM_TOT (2 * SEG_W + 2 * SEG_F)

__global__ void __launch_bounds__(256, 2)
pass1_wmma(const float* __restrict__ feat, const float* __restrict__ fw,
           const float* __restrict__ fg, const float* __restrict__ fb,
           const float* __restrict__ fm, const float* __restrict__ fv) {
    extern __shared__ __align__(16) char sm[];
    __nv_bfloat16* Whi = (__nv_bfloat16*)(sm);
    __nv_bfloat16* Wlo = (__nv_bfloat16*)(sm + SEG_W);
    __nv_bfloat16* Fhi = (__nv_bfloat16*)(sm + 2 * SEG_W);
    __nv_bfloat16* Flo = (__nv_bfloat16*)(sm + 2 * SEG_W + SEG_F);
    __shared__ float s_sf[128], s_hf[128];

    const int tid = threadIdx.x;
    const int gp0 = blockIdx.x * NPXT;
    const int b   = gp0 >> 15;
    const int p0  = gp0 & (HW - 1);

    // ---- fold BN scale/shift (128 threads) ----
    if (tid < 128) {
        float sf = fg[tid] * rsqrtf(fv[tid] + EPS);
        s_sf[tid] = sf;
        s_hf[tid] = fb[tid] - fm[tid] * sf;
    }

    // ---- F tile fp32 -> bf16 hi/lo, [px][k] padded smem (no deps on sf) ----
    {
        const float* fbase = feat + b * Cc * HW + p0;
        const int px = tid & 63;
        const int kg = tid >> 6;                 // 0..3 (32 k each)
        char* fhiRow = (char*)Fhi + px * (LDW * 2);
        char* floRow = (char*)Flo + px * (LDW * 2);
        #pragma unroll 8
        for (int j = 0; j < 16; j++) {
            int k = kg * 32 + 2 * j;
            float f0 = __ldg(fbase + k * HW + px);
            float f1 = __ldg(fbase + (k + 1) * HW + px);
            __nv_bfloat16 h0 = __float2bfloat16(f0);
            __nv_bfloat16 h1 = __float2bfloat16(f1);
            uint32_t vh = (uint32_t)__bfloat16_as_ushort(h0) | ((uint32_t)__bfloat16_as_ushort(h1) << 16);
            uint32_t vl = pack_bf2(f0 - __bfloat162float(h0), f1 - __bfloat162float(h1));
            *(uint32_t*)(fhiRow + 2 * k) = vh;
            *(uint32_t*)(floRow + 2 * k) = vl;
        }
    }
    __syncthreads();

    // ---- W split: fw * sf -> bf16 hi/lo into padded smem ----
    {
        const float4* fw4 = (const float4*)fw;
        #pragma unroll
        for (int it = 0; it < 16; it++) {
            int idx4 = tid + (it << 8);          // 0..4095
            int o = idx4 >> 5, s = idx4 & 31;
            float4 w4 = __ldg(fw4 + idx4);
            float sf = s_sf[o];
            float w0 = w4.x * sf, w1 = w4.y * sf, w2 = w4.z * sf, w3 = w4.w * sf;
            __nv_bfloat16 h0 = __float2bfloat16(w0), h1 = __float2bfloat16(w1);
            __nv_bfloat16 h2 = __float2bfloat16(w2), h3 = __float2bfloat16(w3);
            uint2 hv, lv;
            hv.x = (uint32_t)__bfloat16_as_ushort(h0) | ((uint32_t)__bfloat16_as_ushort(h1) << 16);
            hv.y = (uint32_t)__bfloat16_as_ushort(h2) | ((uint32_t)__bfloat16_as_ushort(h3) << 16);
            lv.x = pack_bf2(w0 - __bfloat162float(h0), w1 - __bfloat162float(h1));
            lv.y = pack_bf2(w2 - __bfloat162float(h2), w3 - __bfloat162float(h3));
            *(uint2*)((char*)Whi + o * (LDW * 2) + s * 8) = hv;
            *(uint2*)((char*)Wlo + o * (LDW * 2) + s * 8) = lv;
        }
    }
    __syncthreads();

    // ---- wmma mainloop: 8 warps, each 32(out) x 32(px) ----
    const int wid = tid >> 5;
    const int wm  = wid & 3;
    const int wn  = wid >> 2;

    wmma::fragment<wmma::accumulator, 16, 16, 16, float> c[2][2];
    #pragma unroll
    for (int i = 0; i < 2; i++)
        #pragma unroll
        for (int j = 0; j < 2; j++) wmma::fill_fragment(c[i][j], 0.f);

    #pragma unroll
    for (int ks = 0; ks < 8; ks++) {
        const int k0 = ks * 16;
        wmma::fragment<wmma::matrix_a, 16, 16, 16, __nv_bfloat16, wmma::row_major> ah[2], al[2];
        wmma::fragment<wmma::matrix_b, 16, 16, 16, __nv_bfloat16, wmma::col_major> bh[2], bl[2];
        #pragma unroll
        for (int i = 0; i < 2; i++) {
            int m0 = wm * 32 + i * 16;
            wmma::load_matrix_sync(ah[i], Whi + m0 * LDW + k0, LDW);
            wmma::load_matrix_sync(al[i], Wlo + m0 * LDW + k0, LDW);
        }
        #pragma unroll
        for (int j = 0; j < 2; j++) {
            int n0 = wn * 32 + j * 16;
            wmma::load_matrix_sync(bh[j], Fhi + n0 * LDW + k0, LDW);
            wmma::load_matrix_sync(bl[j], Flo + n0 * LDW + k0, LDW);
        }
        #pragma unroll
        for (int i = 0; i < 2; i++)
            #pragma unroll
            for (int j = 0; j < 2; j++) {
                wmma::mma_sync(c[i][j], ah[i], bh[j], c[i][j]);
                wmma::mma_sync(c[i][j], ah[i], bl[j], c[i][j]);
                wmma::mma_sync(c[i][j], al[i], bh[j], c[i][j]);
            }
    }
    __syncthreads();

    // ---- stage accumulators (reuse F region), relu(+hf), coalesced STG ----
    float* stage = (float*)(sm + 2 * SEG_W);   // [128][LDST]
    #pragma unroll
    for (int i = 0; i < 2; i++)
        #pragma unroll
        for (int j = 0; j < 2; j++)
            wmma::store_matrix_sync(stage + (wm * 32 + i * 16) * LDST + wn * 32 + j * 16,
                                    c[i][j], LDST, wmma::mem_row_major);
    __syncthreads();

    const int lid = tid & 31;
    const int f4  = lid & 15;
    const int ro  = lid >> 4;
    #pragma unroll
    for (int j = 0; j < 8; j++) {
        int o = wid * 16 + 2 * j + ro;
        float hf = s_hf[o];
        float4 v = *(float4*)&stage[o * LDST + f4 * 4];
        v.x = fmaxf(v.x + hf, 0.f);
        v.y = fmaxf(v.y + hf, 0.f);
        v.z = fmaxf(v.z + hf, 0.f);
        v.w = fmaxf(v.w + hf, 0.f);
        *(float4*)(g_Y + o * NPIX + gp0 + f4 * 4) = v;
    }
}

// ---------------------------------------------------------------- pass2
// grid (512 strips, 4 channel groups), 128 threads. Per channel: stage 3 Y
// rows (mask/border kill folded as -1e30) into double-buffered smem, 9-LDS
// window max. Params folded per block. Partial ew sums -> g_E.
__global__ void __launch_bounds__(128)
pass2_kernel(const float* __restrict__ cart, const unsigned int* __restrict__ mk,
             float* __restrict__ out_geo,
             const float* __restrict__ pw,
             const float* __restrict__ pg, const float* __restrict__ pb,
             const float* __restrict__ pm, const float* __restrict__ pv,
             const float* __restrict__ ew,
             const float* __restrict__ eg, const float* __restrict__ ev) {
    __shared__ float4 s_pw[32];
    __shared__ float4 s_ew[32];
    __shared__ float  sY[2][3][132];

    const int t    = threadIdx.x;
    const int grp  = blockIdx.y;
    const int o0   = grp << 5;

    if (t < 32) {
        int o = o0 + t;
        float sp = pg[o] * rsqrtf(pv[o] + EPS);
        float hp = pb[o] - pm[o] * sp;
        s_pw[t] = make_float4(pw[3*o]*sp, pw[3*o+1]*sp, pw[3*o+2]*sp, hp);
        float se0 = eg[0] * rsqrtf(ev[0] + EPS);
        float se1 = eg[1] * rsqrtf(ev[1] + EPS);
        float se2 = eg[2] * rsqrtf(ev[2] + EPS);
        s_ew[t] = make_float4(ew[o]*se0, ew[Cc+o]*se1, ew[2*Cc+o]*se2, 0.f);
    }

    const int gp = (blockIdx.x << 7) + t;
    const int b  = gp >> 15;
    const int p  = gp & (HW - 1);
    const int y  = p >> 9;
    const int x  = p & (Wd - 1);
    const int x0 = x & ~127;
    const int bbase = b << 15;

    // row bases (clamped) + validity
    int  rowp[3];
    bool rowv[3];
#pragma unroll
    for (int r = 0; r < 3; r++) {
        int yy = y - 1 + r;
        rowv[r] = (yy >= 0) && (yy < Hd);
        rowp[r] = bbase + (rowv[r] ? yy : y) * Wd;
    }

    // per-thread kill (own column)
    float kr[3];
#pragma unroll
    for (int r = 0; r < 3; r++)
        kr[r] = (rowv[r] && (__ldg(mk + rowp[r] + x) != 0u)) ? 0.f : KILLV;

    // edge cells: threads 0..5 own (row r, side s)
    const bool eact = (t < 6);
    int er = 0, ecol = 0, eoff = 0;
    float ekill = KILLV;
    if (eact) {
        er = t >> 1;
        int side = t & 1;
        int ex = side ? (x0 + 128) : (x0 - 1);
        bool cv = side ? (x0 + 128 < Wd) : (x0 > 0);
        int exc = cv ? ex : x0;
        eoff = rowp[er] + exc;
        ecol = side ? 129 : 0;
        ekill = (rowv[er] && cv && (__ldg(mk + eoff) != 0u)) ? 0.f : KILLV;
    }

    // relative coordinates (garbage where killed — harmless, kill dominates)
    const float* cb = cart + b * 3 * HW;
    const float ccx = __ldg(cb + p);
    const float ccy = __ldg(cb + HW + p);
    const float ccz = __ldg(cb + 2 * HW + p);
    float rx[9], ry[9], rz[9];
#pragma unroll
    for (int kh = 0; kh < 3; kh++) {
#pragma unroll
        for (int kw = 0; kw < 3; kw++) {
            int n = kh * 3 + kw;
            int xx = x + kw - 1;
            int pl = (rowp[kh] & (HW - 1)) + ((xx >= 0 && xx < Wd) ? xx : x);
            rx[n] = __ldg(cb + pl) - ccx;
            ry[n] = __ldg(cb + HW + pl) - ccy;
            rz[n] = __ldg(cb + 2 * HW + pl) - ccz;
        }
    }
    __syncthreads();   // s_pw / s_ew ready

    // prefetch channel o0
    float yv[3], yedge = 0.f;
    {
        const float* Yo = g_Y + o0 * NPIX;
#pragma unroll
        for (int r = 0; r < 3; r++) yv[r] = __ldg(Yo + rowp[r] + x) + kr[r];
        if (eact) yedge = __ldg(Yo + eoff) + ekill;
    }

    float e0 = 0.f, e1 = 0.f, e2 = 0.f;
    float* og = out_geo + b * Cc * HW + p;

    for (int oc = 0; oc < 32; oc++) {
        const int cur = oc & 1;
        sY[cur][0][t + 1] = yv[0];
        sY[cur][1][t + 1] = yv[1];
        sY[cur][2][t + 1] = yv[2];
        if (eact) sY[cur][er][ecol] = yedge;
        __syncthreads();

        if (oc < 31) {
            const float* Yn = g_Y + (o0 + oc + 1) * NPIX;
#pragma unroll
            for (int r = 0; r < 3; r++) yv[r] = __ldg(Yn + rowp[r] + x) + kr[r];
            if (eact) yedge = __ldg(Yn + eoff) + ekill;
        }

        const float4 pwv = s_pw[oc];
        float gm = 0.f;
#pragma unroll
        for (int kh = 0; kh < 3; kh++) {
#pragma unroll
            for (int kw = 0; kw < 3; kw++) {
                int n = kh * 3 + kw;
                float d = fmaf(pwv.x, rx[n], fmaf(pwv.y, ry[n], fmaf(pwv.z, rz[n], pwv.w)));
                float fe = sY[cur][kh][t + kw] + fmaxf(d, 0.f);
                gm = fmaxf(gm, fe);
            }
        }
        og[(o0 + oc) * HW] = gm;
        const float4 e = s_ew[oc];
        e0 = fmaf(e.x, gm, e0);
        e1 = fmaf(e.y, gm, e1);
        e2 = fmaf(e.z, gm, e2);
    }

    g_E[(0 * 4 + grp) * NPIX + gp] = e0;
    g_E[(1 * 4 + grp) * NPIX + gp] = e1;
    g_E[(2 * 4 + grp) * NPIX + gp] = e2;
}

// ---------------------------------------------------------------- fixup (cart_out)
// thread per (k, pixel): 768 blocks x 256 threads.
__global__ void __launch_bounds__(256)
fixup_kernel(const float* __restrict__ cart, const unsigned int* __restrict__ mk,
             float* __restrict__ out_cart,
             const float* __restrict__ eg, const float* __restrict__ eb,
             const float* __restrict__ em, const float* __restrict__ ev) {
    const int gid = blockIdx.x * 256 + threadIdx.x;   // 0..3*NPIX-1
    const int k  = gid >> 16;
    const int r  = gid & (NPIX - 1);
    const int b  = r >> 15;
    const int p  = r & (HW - 1);
    float se  = eg[k] * rsqrtf(ev[k] + EPS);
    float she = eb[k] - em[k] * se;
    const float* Ek = g_E + k * 4 * NPIX;
    float s = Ek[r] + Ek[NPIX + r] + Ek[2 * NPIX + r] + Ek[3 * NPIX + r];
    const float mc = (__ldg(mk + r) != 0u) ? 1.f : 0.f;
    int ci = (b * 3 + k) * HW + p;
    out_cart[ci] = __ldg(cart + ci) + (s + she) * mc;
}

// ---------------------------------------------------------------- launch
extern "C" void kernel_launch(void* const* d_in, const int* in_sizes, int n_in,
                              void* d_out, int out_size) {
    const float* feat = (const float*)d_in[0];
    const float* cart = (const float*)d_in[1];
    const unsigned int* mask = (const unsigned int*)d_in[2];
    const float* pw = (const float*)d_in[3];
    const float* pg = (const float*)d_in[4];
    const float* pb = (const float*)d_in[5];
    const float* pm = (const float*)d_in[6];
    const float* pv = (const float*)d_in[7];
    const float* fw = (const float*)d_in[8];
    const float* fg = (const float*)d_in[9];
    const float* fb = (const float*)d_in[10];
    const float* fm = (const float*)d_in[11];
    const float* fv = (const float*)d_in[12];
    const float* ew = (const float*)d_in[13];
    const float* eg = (const float*)d_in[14];
    const float* eb = (const float*)d_in[15];
    const float* em = (const float*)d_in[16];
    const float* ev = (const float*)d_in[17];
    (void)in_sizes; (void)n_in; (void)out_size;

    float* out_geo  = (float*)d_out;                        // (B,128,H,W)
    float* out_cart = (float*)d_out + (size_t)Bd * Cc * HW; // (B,3,H,W)

    cudaFuncSetAttribute(pass1_wmma, cudaFuncAttributeMaxDynamicSharedMemorySize, SM_TOT);

    pass1_wmma<<<NPIX / NPXT, 256, SM_TOT>>>(feat, fw, fg, fb, fm, fv);
    dim3 g2(NPIX / 128, 4);
    pass2_kernel<<<g2, 128>>>(cart, mask, out_geo, pw, pg, pb, pm, pv, ew, eg, ev);
    fixup_kernel<<<3 * NPIX / 256, 256>>>(cart, mask, out_cart, eg, eb, em, ev);
}

// round 14
// speedup vs baseline: 1.0739x; 1.0739x over previous
#include <cuda_runtime.h>
#include <cuda_bf16.h>
#include <mma.h>
#include <cstdint>

using namespace nvcuda;

#define Bd   2
#define Cc   128
#define Hd   64
#define Wd   512
#define HW   (Hd*Wd)          // 32768
#define NPIX (Bd*HW)          // 65536
#define EPS  1e-5f

#define LDW   136             // bf16 leading dim in smem (272B rows)
#define NPXT  64              // px per pass1 block
#define LDST  68              // f32 stage leading dim
#define NGRP  8               // pass2 channel groups
#define CPG   (Cc/NGRP)       // 16 channels per group

// ---------------- device scratch (allocation-free) ----------------
__device__ __align__(16) float g_Y[Cc * NPIX];        // [o][gp]
__device__ __align__(16) float g_E[3 * NGRP * NPIX];  // [k*NGRP+grp][gp]

__device__ __forceinline__ uint32_t pack_bf2(float a, float b) {
    __nv_bfloat16 ha = __float2bfloat16(a), hb = __float2bfloat16(b);
    return (uint32_t)__bfloat16_as_ushort(ha) | ((uint32_t)__bfloat16_as_ushort(hb) << 16);
}

// ---------------------------------------------------------------- pass1 (wmma, 2 CTA/SM)
// Per block: D[128 out][64 px] = (Whi+Wlo) x (Fhi+Flo)^T, 3-term bf16 split.
// BN fold + W split in-block. F-convert uses STS.128 (conflict-free phases).
#define SEG_W 34816
#define SEG_F 17408
#define SM_TOT (2 * SEG_W + 2 * SEG_F)

__global__ void __launch_bounds__(256, 2)
pass1_wmma(const float* __restrict__ feat, const float* __restrict__ fw,
           const float* __restrict__ fg, const float* __restrict__ fb,
           const float* __restrict__ fm, const float* __restrict__ fv) {
    extern __shared__ __align__(16) char sm[];
    __nv_bfloat16* Whi = (__nv_bfloat16*)(sm);
    __nv_bfloat16* Wlo = (__nv_bfloat16*)(sm + SEG_W);
    __nv_bfloat16* Fhi = (__nv_bfloat16*)(sm + 2 * SEG_W);
    __nv_bfloat16* Flo = (__nv_bfloat16*)(sm + 2 * SEG_W + SEG_F);
    __shared__ float s_sf[128], s_hf[128];

    const int tid = threadIdx.x;
    const int gp0 = blockIdx.x * NPXT;
    const int b   = gp0 >> 15;
    const int p0  = gp0 & (HW - 1);

    // ---- fold BN scale/shift ----
    if (tid < 128) {
        float sf = fg[tid] * rsqrtf(fv[tid] + EPS);
        s_sf[tid] = sf;
        s_hf[tid] = fb[tid] - fm[tid] * sf;
    }

    // ---- F tile fp32 -> bf16 hi/lo, [px][k], STS.128 (8 k per store) ----
    {
        const float* fbase = feat + b * Cc * HW + p0;
        const int px = tid & 63;
        const int kg = tid >> 6;                 // 0..3 (32 k each)
        char* fhiRow = (char*)Fhi + px * (LDW * 2) + kg * 64;
        char* floRow = (char*)Flo + px * (LDW * 2) + kg * 64;
        #pragma unroll
        for (int j4 = 0; j4 < 4; j4++) {
            uint32_t vh[4], vl[4];
            #pragma unroll
            for (int m = 0; m < 4; m++) {
                int k = kg * 32 + 8 * j4 + 2 * m;
                float f0 = __ldg(fbase + k * HW + px);
                float f1 = __ldg(fbase + (k + 1) * HW + px);
                __nv_bfloat16 h0 = __float2bfloat16(f0);
                __nv_bfloat16 h1 = __float2bfloat16(f1);
                vh[m] = (uint32_t)__bfloat16_as_ushort(h0) | ((uint32_t)__bfloat16_as_ushort(h1) << 16);
                vl[m] = pack_bf2(f0 - __bfloat162float(h0), f1 - __bfloat162float(h1));
            }
            *(uint4*)(fhiRow + 16 * j4) = make_uint4(vh[0], vh[1], vh[2], vh[3]);
            *(uint4*)(floRow + 16 * j4) = make_uint4(vl[0], vl[1], vl[2], vl[3]);
        }
    }
    __syncthreads();

    // ---- W split: fw * sf -> bf16 hi/lo ----
    {
        const float4* fw4 = (const float4*)fw;
        #pragma unroll
        for (int it = 0; it < 16; it++) {
            int idx4 = tid + (it << 8);          // 0..4095
            int o = idx4 >> 5, s = idx4 & 31;
            float4 w4 = __ldg(fw4 + idx4);
            float sf = s_sf[o];
            float w0 = w4.x * sf, w1 = w4.y * sf, w2 = w4.z * sf, w3 = w4.w * sf;
            __nv_bfloat16 h0 = __float2bfloat16(w0), h1 = __float2bfloat16(w1);
            __nv_bfloat16 h2 = __float2bfloat16(w2), h3 = __float2bfloat16(w3);
            uint2 hv, lv;
            hv.x = (uint32_t)__bfloat16_as_ushort(h0) | ((uint32_t)__bfloat16_as_ushort(h1) << 16);
            hv.y = (uint32_t)__bfloat16_as_ushort(h2) | ((uint32_t)__bfloat16_as_ushort(h3) << 16);
            lv.x = pack_bf2(w0 - __bfloat162float(h0), w1 - __bfloat162float(h1));
            lv.y = pack_bf2(w2 - __bfloat162float(h2), w3 - __bfloat162float(h3));
            *(uint2*)((char*)Whi + o * (LDW * 2) + s * 8) = hv;
            *(uint2*)((char*)Wlo + o * (LDW * 2) + s * 8) = lv;
        }
    }
    __syncthreads();

    // ---- wmma mainloop: 8 warps, each 32(out) x 32(px) ----
    const int wid = tid >> 5;
    const int wm  = wid & 3;
    const int wn  = wid >> 2;

    wmma::fragment<wmma::accumulator, 16, 16, 16, float> c[2][2];
    #pragma unroll
    for (int i = 0; i < 2; i++)
        #pragma unroll
        for (int j = 0; j < 2; j++) wmma::fill_fragment(c[i][j], 0.f);

    #pragma unroll
    for (int ks = 0; ks < 8; ks++) {
        const int k0 = ks * 16;
        wmma::fragment<wmma::matrix_a, 16, 16, 16, __nv_bfloat16, wmma::row_major> ah[2], al[2];
        wmma::fragment<wmma::matrix_b, 16, 16, 16, __nv_bfloat16, wmma::col_major> bh[2], bl[2];
        #pragma unroll
        for (int i = 0; i < 2; i++) {
            int m0 = wm * 32 + i * 16;
            wmma::load_matrix_sync(ah[i], Whi + m0 * LDW + k0, LDW);
            wmma::load_matrix_sync(al[i], Wlo + m0 * LDW + k0, LDW);
        }
        #pragma unroll
        for (int j = 0; j < 2; j++) {
            int n0 = wn * 32 + j * 16;
            wmma::load_matrix_sync(bh[j], Fhi + n0 * LDW + k0, LDW);
            wmma::load_matrix_sync(bl[j], Flo + n0 * LDW + k0, LDW);
        }
        #pragma unroll
        for (int i = 0; i < 2; i++)
            #pragma unroll
            for (int j = 0; j < 2; j++) {
                wmma::mma_sync(c[i][j], ah[i], bh[j], c[i][j]);
                wmma::mma_sync(c[i][j], ah[i], bl[j], c[i][j]);
                wmma::mma_sync(c[i][j], al[i], bh[j], c[i][j]);
            }
    }
    __syncthreads();

    // ---- stage accumulators (reuse F region), relu(+hf), coalesced STG ----
    float* stage = (float*)(sm + 2 * SEG_W);   // [128][LDST]
    #pragma unroll
    for (int i = 0; i < 2; i++)
        #pragma unroll
        for (int j = 0; j < 2; j++)
            wmma::store_matrix_sync(stage + (wm * 32 + i * 16) * LDST + wn * 32 + j * 16,
                                    c[i][j], LDST, wmma::mem_row_major);
    __syncthreads();

    const int lid = tid & 31;
    const int f4  = lid & 15;
    const int ro  = lid >> 4;
    #pragma unroll
    for (int j = 0; j < 8; j++) {
        int o = wid * 16 + 2 * j + ro;
        float hf = s_hf[o];
        float4 v = *(float4*)&stage[o * LDST + f4 * 4];
        v.x = fmaxf(v.x + hf, 0.f);
        v.y = fmaxf(v.y + hf, 0.f);
        v.z = fmaxf(v.z + hf, 0.f);
        v.w = fmaxf(v.w + hf, 0.f);
        *(float4*)(g_Y + o * NPIX + gp0 + f4 * 4) = v;
    }
}

// ---------------------------------------------------------------- pass2 (R7 body, 8-way split)
__global__ void __launch_bounds__(128)
pass2_kernel(const float* __restrict__ cart, const unsigned int* __restrict__ mk,
             float* __restrict__ out_geo,
             const float* __restrict__ pw,
             const float* __restrict__ pg, const float* __restrict__ pb,
             const float* __restrict__ pm, const float* __restrict__ pv,
             const float* __restrict__ ew,
             const float* __restrict__ eg, const float* __restrict__ ev) {
    __shared__ float4 s_pw[CPG];
    __shared__ float4 s_ew[CPG];

    const int t   = threadIdx.x;
    const int grp = blockIdx.y;
    const int o0  = grp * CPG;

    if (t < CPG) {
        int o = o0 + t;
        float sp = pg[o] * rsqrtf(pv[o] + EPS);
        float hp = pb[o] - pm[o] * sp;
        s_pw[t] = make_float4(pw[3*o]*sp, pw[3*o+1]*sp, pw[3*o+2]*sp, hp);
        float se0 = eg[0] * rsqrtf(ev[0] + EPS);
        float se1 = eg[1] * rsqrtf(ev[1] + EPS);
        float se2 = eg[2] * rsqrtf(ev[2] + EPS);
        s_ew[t] = make_float4(ew[o]*se0, ew[Cc+o]*se1, ew[2*Cc+o]*se2, 0.f);
    }

    const int gp = (blockIdx.x << 7) + t;
    const int b  = gp >> 15;
    const int p  = gp & (HW - 1);
    const int y  = p >> 9;
    const int x  = p & (Wd - 1);

    const float* cb = cart + b * 3 * HW;
    const float ccx = __ldg(cb + p);
    const float ccy = __ldg(cb + HW + p);
    const float ccz = __ldg(cb + 2 * HW + p);

    int   off[9];
    float am[9], rx[9], ry[9], rz[9];
#pragma unroll
    for (int kh = 0; kh < 3; kh++) {
#pragma unroll
        for (int kw = 0; kw < 3; kw++) {
            int n = kh * 3 + kw;
            int yy = y + kh - 1, xx = x + kw - 1;
            bool v = (yy >= 0) && (yy < Hd) && (xx >= 0) && (xx < Wd);
            int pn = yy * Wd + xx;
            int o  = v ? ((b << 15) + pn) : gp;
            off[n] = o;
            am[n]  = (v && (__ldg(mk + o) != 0u)) ? 1.f : 0.f;
            int pl = o & (HW - 1);
            rx[n] = __ldg(cb + pl) - ccx;
            ry[n] = __ldg(cb + HW + pl) - ccy;
            rz[n] = __ldg(cb + 2 * HW + pl) - ccz;
        }
    }
    __syncthreads();

    float e0 = 0.f, e1 = 0.f, e2 = 0.f;
    float* og = out_geo + b * Cc * HW + p;

#pragma unroll 2
    for (int oc = 0; oc < CPG; oc++) {
        const int o = o0 + oc;
        const float4 pwv = s_pw[oc];
        const float* Yo = g_Y + o * NPIX;
        float gm = 0.f;
#pragma unroll
        for (int n = 0; n < 9; n++) {
            float pos = fmaxf(fmaf(pwv.x, rx[n], fmaf(pwv.y, ry[n], fmaf(pwv.z, rz[n], pwv.w))), 0.f);
            float fe  = __ldg(Yo + off[n]) + pos;
            gm = fmaxf(gm, am[n] * fe);
        }
        og[o * HW] = gm;
        const float4 e = s_ew[oc];
        e0 = fmaf(e.x, gm, e0);
        e1 = fmaf(e.y, gm, e1);
        e2 = fmaf(e.z, gm, e2);
    }

    g_E[(0 * NGRP + grp) * NPIX + gp] = e0;
    g_E[(1 * NGRP + grp) * NPIX + gp] = e1;
    g_E[(2 * NGRP + grp) * NPIX + gp] = e2;
}

// ---------------------------------------------------------------- fixup (cart_out)
// thread per (k, pixel)
__global__ void __launch_bounds__(256)
fixup_kernel(const float* __restrict__ cart, const unsigned int* __restrict__ mk,
             float* __restrict__ out_cart,
             const float* __restrict__ eg, const float* __restrict__ eb,
             const float* __restrict__ em, const float* __restrict__ ev) {
    const int gid = blockIdx.x * 256 + threadIdx.x;   // 0..3*NPIX-1
    const int k  = gid >> 16;
    const int r  = gid & (NPIX - 1);
    const int b  = r >> 15;
    const int p  = r & (HW - 1);
    float se  = eg[k] * rsqrtf(ev[k] + EPS);
    float she = eb[k] - em[k] * se;
    const float* Ek = g_E + k * NGRP * NPIX;
    float s = 0.f;
#pragma unroll
    for (int g = 0; g < NGRP; g++) s += Ek[g * NPIX + r];
    const float mc = (__ldg(mk + r) != 0u) ? 1.f : 0.f;
    int ci = (b * 3 + k) * HW + p;
    out_cart[ci] = __ldg(cart + ci) + (s + she) * mc;
}

// ---------------------------------------------------------------- launch
extern "C" void kernel_launch(void* const* d_in, const int* in_sizes, int n_in,
                              void* d_out, int out_size) {
    const float* feat = (const float*)d_in[0];
    const float* cart = (const float*)d_in[1];
    const unsigned int* mask = (const unsigned int*)d_in[2];
    const float* pw = (const float*)d_in[3];
    const float* pg = (const float*)d_in[4];
    const float* pb = (const float*)d_in[5];
    const float* pm = (const float*)d_in[6];
    const float* pv = (const float*)d_in[7];
    const float* fw = (const float*)d_in[8];
    const float* fg = (const float*)d_in[9];
    const float* fb = (const float*)d_in[10];
    const float* fm = (const float*)d_in[11];
    const float* fv = (const float*)d_in[12];
    const float* ew = (const float*)d_in[13];
    const float* eg = (const float*)d_in[14];
    const float* eb = (const float*)d_in[15];
    const float* em = (const float*)d_in[16];
    const float* ev = (const float*)d_in[17];
    (void)in_sizes; (void)n_in; (void)out_size;

    float* out_geo  = (float*)d_out;                        // (B,128,H,W)
    float* out_cart = (float*)d_out + (size_t)Bd * Cc * HW; // (B,3,H,W)

    cudaFuncSetAttribute(pass1_wmma, cudaFuncAttributeMaxDynamicSharedMemorySize, SM_TOT);

    pass1_wmma<<<NPIX / NPXT, 256, SM_TOT>>>(feat, fw, fg, fb, fm, fv);
    dim3 g2(NPIX / 128, NGRP);
    pass2_kernel<<<g2, 128>>>(cart, mask, out_geo, pw, pg, pb, pm, pv, ew, eg, ev);
    fixup_kernel<<<3 * NPIX / 256, 256>>>(cart, mask, out_cart, eg, eb, em, ev);
}

// round 15
// speedup vs baseline: 1.0943x; 1.0190x over previous
#include <cuda_runtime.h>
#include <cuda_bf16.h>
#include <mma.h>
#include <cstdint>

using namespace nvcuda;

#define Bd   2
#define Cc   128
#define Hd   64
#define Wd   512
#define HW   (Hd*Wd)          // 32768
#define NPIX (Bd*HW)          // 65536
#define EPS  1e-5f

#define LDW   136             // bf16 leading dim in smem (272B rows)
#define NPXT  64              // px per pass1 block
#define LDST  68              // f32 stage leading dim
#define NGRP  4               // pass2 channel groups (R7-proven)
#define CPG   (Cc/NGRP)       // 32 channels per group
#define KILLB (-1e30f)

// ---------------- device scratch (allocation-free) ----------------
__device__ __align__(16) float g_Y[Cc * NPIX];        // [o][gp]
__device__ __align__(16) float g_E[3 * NGRP * NPIX];  // [k*NGRP+grp][gp]

__device__ __forceinline__ uint32_t pack_bf2(float a, float b) {
    __nv_bfloat16 ha = __float2bfloat16(a), hb = __float2bfloat16(b);
    return (uint32_t)__bfloat16_as_ushort(ha) | ((uint32_t)__bfloat16_as_ushort(hb) << 16);
}

// ---------------------------------------------------------------- pass1 (wmma, 2 CTA/SM)
// R12-proven: D[128 out][64 px] = (Whi+Wlo) x (Fhi+Flo)^T, 3-term bf16 split.
#define SEG_W 34816
#define SEG_F 17408
#define SM_TOT (2 * SEG_W + 2 * SEG_F)

__global__ void __launch_bounds__(256, 2)
pass1_wmma(const float* __restrict__ feat, const float* __restrict__ fw,
           const float* __restrict__ fg, const float* __restrict__ fb,
           const float* __restrict__ fm, const float* __restrict__ fv) {
    extern __shared__ __align__(16) char sm[];
    __nv_bfloat16* Whi = (__nv_bfloat16*)(sm);
    __nv_bfloat16* Wlo = (__nv_bfloat16*)(sm + SEG_W);
    __nv_bfloat16* Fhi = (__nv_bfloat16*)(sm + 2 * SEG_W);
    __nv_bfloat16* Flo = (__nv_bfloat16*)(sm + 2 * SEG_W + SEG_F);
    __shared__ float s_sf[128], s_hf[128];

    const int tid = threadIdx.x;
    const int gp0 = blockIdx.x * NPXT;
    const int b   = gp0 >> 15;
    const int p0  = gp0 & (HW - 1);

    if (tid < 128) {
        float sf = fg[tid] * rsqrtf(fv[tid] + EPS);
        s_sf[tid] = sf;
        s_hf[tid] = fb[tid] - fm[tid] * sf;
    }

    // ---- F tile fp32 -> bf16 hi/lo, [px][k], STS.128 ----
    {
        const float* fbase = feat + b * Cc * HW + p0;
        const int px = tid & 63;
        const int kg = tid >> 6;                 // 0..3
        char* fhiRow = (char*)Fhi + px * (LDW * 2) + kg * 64;
        char* floRow = (char*)Flo + px * (LDW * 2) + kg * 64;
        #pragma unroll
        for (int j4 = 0; j4 < 4; j4++) {
            uint32_t vh[4], vl[4];
            #pragma unroll
            for (int m = 0; m < 4; m++) {
                int k = kg * 32 + 8 * j4 + 2 * m;
                float f0 = __ldg(fbase + k * HW + px);
                float f1 = __ldg(fbase + (k + 1) * HW + px);
                __nv_bfloat16 h0 = __float2bfloat16(f0);
                __nv_bfloat16 h1 = __float2bfloat16(f1);
                vh[m] = (uint32_t)__bfloat16_as_ushort(h0) | ((uint32_t)__bfloat16_as_ushort(h1) << 16);
                vl[m] = pack_bf2(f0 - __bfloat162float(h0), f1 - __bfloat162float(h1));
            }
            *(uint4*)(fhiRow + 16 * j4) = make_uint4(vh[0], vh[1], vh[2], vh[3]);
            *(uint4*)(floRow + 16 * j4) = make_uint4(vl[0], vl[1], vl[2], vl[3]);
        }
    }
    __syncthreads();

    // ---- W split: fw * sf -> bf16 hi/lo ----
    {
        const float4* fw4 = (const float4*)fw;
        #pragma unroll
        for (int it = 0; it < 16; it++) {
            int idx4 = tid + (it << 8);
            int o = idx4 >> 5, s = idx4 & 31;
            float4 w4 = __ldg(fw4 + idx4);
            float sf = s_sf[o];
            float w0 = w4.x * sf, w1 = w4.y * sf, w2 = w4.z * sf, w3 = w4.w * sf;
            __nv_bfloat16 h0 = __float2bfloat16(w0), h1 = __float2bfloat16(w1);
            __nv_bfloat16 h2 = __float2bfloat16(w2), h3 = __float2bfloat16(w3);
            uint2 hv, lv;
            hv.x = (uint32_t)__bfloat16_as_ushort(h0) | ((uint32_t)__bfloat16_as_ushort(h1) << 16);
            hv.y = (uint32_t)__bfloat16_as_ushort(h2) | ((uint32_t)__bfloat16_as_ushort(h3) << 16);
            lv.x = pack_bf2(w0 - __bfloat162float(h0), w1 - __bfloat162float(h1));
            lv.y = pack_bf2(w2 - __bfloat162float(h2), w3 - __bfloat162float(h3));
            *(uint2*)((char*)Whi + o * (LDW * 2) + s * 8) = hv;
            *(uint2*)((char*)Wlo + o * (LDW * 2) + s * 8) = lv;
        }
    }
    __syncthreads();

    // ---- wmma mainloop: 8 warps, each 32(out) x 32(px) ----
    const int wid = tid >> 5;
    const int wm  = wid & 3;
    const int wn  = wid >> 2;

    wmma::fragment<wmma::accumulator, 16, 16, 16, float> c[2][2];
    #pragma unroll
    for (int i = 0; i < 2; i++)
        #pragma unroll
        for (int j = 0; j < 2; j++) wmma::fill_fragment(c[i][j], 0.f);

    #pragma unroll
    for (int ks = 0; ks < 8; ks++) {
        const int k0 = ks * 16;
        wmma::fragment<wmma::matrix_a, 16, 16, 16, __nv_bfloat16, wmma::row_major> ah[2], al[2];
        wmma::fragment<wmma::matrix_b, 16, 16, 16, __nv_bfloat16, wmma::col_major> bh[2], bl[2];
        #pragma unroll
        for (int i = 0; i < 2; i++) {
            int m0 = wm * 32 + i * 16;
            wmma::load_matrix_sync(ah[i], Whi + m0 * LDW + k0, LDW);
            wmma::load_matrix_sync(al[i], Wlo + m0 * LDW + k0, LDW);
        }
        #pragma unroll
        for (int j = 0; j < 2; j++) {
            int n0 = wn * 32 + j * 16;
            wmma::load_matrix_sync(bh[j], Fhi + n0 * LDW + k0, LDW);
            wmma::load_matrix_sync(bl[j], Flo + n0 * LDW + k0, LDW);
        }
        #pragma unroll
        for (int i = 0; i < 2; i++)
            #pragma unroll
            for (int j = 0; j < 2; j++) {
                wmma::mma_sync(c[i][j], ah[i], bh[j], c[i][j]);
                wmma::mma_sync(c[i][j], ah[i], bl[j], c[i][j]);
                wmma::mma_sync(c[i][j], al[i], bh[j], c[i][j]);
            }
    }
    __syncthreads();

    float* stage = (float*)(sm + 2 * SEG_W);   // [128][LDST]
    #pragma unroll
    for (int i = 0; i < 2; i++)
        #pragma unroll
        for (int j = 0; j < 2; j++)
            wmma::store_matrix_sync(stage + (wm * 32 + i * 16) * LDST + wn * 32 + j * 16,
                                    c[i][j], LDST, wmma::mem_row_major);
    __syncthreads();

    const int lid = tid & 31;
    const int f4  = lid & 15;
    const int ro  = lid >> 4;
    #pragma unroll
    for (int j = 0; j < 8; j++) {
        int o = wid * 16 + 2 * j + ro;
        float hf = s_hf[o];
        float4 v = *(float4*)&stage[o * LDST + f4 * 4];
        v.x = fmaxf(v.x + hf, 0.f);
        v.y = fmaxf(v.y + hf, 0.f);
        v.z = fmaxf(v.z + hf, 0.f);
        v.w = fmaxf(v.w + hf, 0.f);
        *(float4*)(g_Y + o * NPIX + gp0 + f4 * 4) = v;
    }
}

// ---------------------------------------------------------------- pass2 (R7 config, reg-trimmed)
// grid (512, 4), 128 threads, 32 ch/block. Mask folded as additive bias
// (fe >= 0, gm clamped at 0, so bias -1e30 kills a neighbor exactly).
__global__ void __launch_bounds__(128)
pass2_kernel(const float* __restrict__ cart, const unsigned int* __restrict__ mk,
             float* __restrict__ out_geo,
             const float* __restrict__ pw,
             const float* __restrict__ pg, const float* __restrict__ pb,
             const float* __restrict__ pm, const float* __restrict__ pv,
             const float* __restrict__ ew,
             const float* __restrict__ eg, const float* __restrict__ ev) {
    __shared__ float4 s_pw[CPG];
    __shared__ float4 s_ew[CPG];

    const int t   = threadIdx.x;
    const int grp = blockIdx.y;
    const int o0  = grp * CPG;

    if (t < CPG) {
        int o = o0 + t;
        float sp = pg[o] * rsqrtf(pv[o] + EPS);
        float hp = pb[o] - pm[o] * sp;
        s_pw[t] = make_float4(pw[3*o]*sp, pw[3*o+1]*sp, pw[3*o+2]*sp, hp);
        float se0 = eg[0] * rsqrtf(ev[0] + EPS);
        float se1 = eg[1] * rsqrtf(ev[1] + EPS);
        float se2 = eg[2] * rsqrtf(ev[2] + EPS);
        s_ew[t] = make_float4(ew[o]*se0, ew[Cc+o]*se1, ew[2*Cc+o]*se2, 0.f);
    }

    const int gp = (blockIdx.x << 7) + t;
    const int b  = gp >> 15;
    const int p  = gp & (HW - 1);
    const int y  = p >> 9;
    const int x  = p & (Wd - 1);

    const float* cb = cart + b * 3 * HW;
    const float ccx = __ldg(cb + p);
    const float ccy = __ldg(cb + HW + p);
    const float ccz = __ldg(cb + 2 * HW + p);

    int   off[9];
    float bias[9], rx[9], ry[9], rz[9];
#pragma unroll
    for (int kh = 0; kh < 3; kh++) {
#pragma unroll
        for (int kw = 0; kw < 3; kw++) {
            int n = kh * 3 + kw;
            int yy = y + kh - 1, xx = x + kw - 1;
            bool v = (yy >= 0) && (yy < Hd) && (xx >= 0) && (xx < Wd);
            int o  = v ? ((b << 15) + yy * Wd + xx) : gp;
            off[n]  = o;
            bias[n] = (v && (__ldg(mk + o) != 0u)) ? 0.f : KILLB;
            int pl = o & (HW - 1);
            rx[n] = __ldg(cb + pl) - ccx;
            ry[n] = __ldg(cb + HW + pl) - ccy;
            rz[n] = __ldg(cb + 2 * HW + pl) - ccz;
        }
    }
    __syncthreads();

    float e0 = 0.f, e1 = 0.f, e2 = 0.f;
    float* og = out_geo + b * Cc * HW + p;

#pragma unroll 2
    for (int oc = 0; oc < CPG; oc++) {
        const int o = o0 + oc;
        const float4 pwv = s_pw[oc];
        const float* Yo = g_Y + o * NPIX;
        float gm = 0.f;
#pragma unroll
        for (int n = 0; n < 9; n++) {
            float pos = fmaxf(fmaf(pwv.x, rx[n], fmaf(pwv.y, ry[n], fmaf(pwv.z, rz[n], pwv.w))), 0.f);
            float fe  = __ldg(Yo + off[n]) + pos + bias[n];
            gm = fmaxf(gm, fe);
        }
        og[o * HW] = gm;
        const float4 e = s_ew[oc];
        e0 = fmaf(e.x, gm, e0);
        e1 = fmaf(e.y, gm, e1);
        e2 = fmaf(e.z, gm, e2);
    }

    g_E[(0 * NGRP + grp) * NPIX + gp] = e0;
    g_E[(1 * NGRP + grp) * NPIX + gp] = e1;
    g_E[(2 * NGRP + grp) * NPIX + gp] = e2;
}

// ---------------------------------------------------------------- fixup (cart_out)
__global__ void __launch_bounds__(256)
fixup_kernel(const float* __restrict__ cart, const unsigned int* __restrict__ mk,
             float* __restrict__ out_cart,
             const float* __restrict__ eg, const float* __restrict__ eb,
             const float* __restrict__ em, const float* __restrict__ ev) {
    const int gid = blockIdx.x * 256 + threadIdx.x;   // 0..3*NPIX-1
    const int k  = gid >> 16;
    const int r  = gid & (NPIX - 1);
    const int b  = r >> 15;
    const int p  = r & (HW - 1);
    float se  = eg[k] * rsqrtf(ev[k] + EPS);
    float she = eb[k] - em[k] * se;
    const float* Ek = g_E + k * NGRP * NPIX;
    float s = 0.f;
#pragma unroll
    for (int g = 0; g < NGRP; g++) s += Ek[g * NPIX + r];
    const float mc = (__ldg(mk + r) != 0u) ? 1.f : 0.f;
    int ci = (b * 3 + k) * HW + p;
    out_cart[ci] = __ldg(cart + ci) + (s + she) * mc;
}

// ---------------------------------------------------------------- launch
extern "C" void kernel_launch(void* const* d_in, const int* in_sizes, int n_in,
                              void* d_out, int out_size) {
    const float* feat = (const float*)d_in[0];
    const float* cart = (const float*)d_in[1];
    const unsigned int* mask = (const unsigned int*)d_in[2];
    const float* pw = (const float*)d_in[3];
    const float* pg = (const float*)d_in[4];
    const float* pb = (const float*)d_in[5];
    const float* pm = (const float*)d_in[6];
    const float* pv = (const float*)d_in[7];
    const float* fw = (const float*)d_in[8];
    const float* fg = (const float*)d_in[9];
    const float* fb = (const float*)d_in[10];
    const float* fm = (const float*)d_in[11];
    const float* fv = (const float*)d_in[12];
    const float* ew = (const float*)d_in[13];
    const float* eg = (const float*)d_in[14];
    const float* eb = (const float*)d_in[15];
    const float* em = (const float*)d_in[16];
    const float* ev = (const float*)d_in[17];
    (void)in_sizes; (void)n_in; (void)out_size;

    float* out_geo  = (float*)d_out;                        // (B,128,H,W)
    float* out_cart = (float*)d_out + (size_t)Bd * Cc * HW; // (B,3,H,W)

    cudaFuncSetAttribute(pass1_wmma, cudaFuncAttributeMaxDynamicSharedMemorySize, SM_TOT);

    pass1_wmma<<<NPIX / NPXT, 256, SM_TOT>>>(feat, fw, fg, fb, fm, fv);
    dim3 g2(NPIX / 128, NGRP);
    pass2_kernel<<<g2, 128>>>(cart, mask, out_geo, pw, pg, pb, pm, pv, ew, eg, ev);
    fixup_kernel<<<3 * NPIX / 256, 256>>>(cart, mask, out_cart, eg, eb, em, ev);
}